// round 13
// baseline (speedup 1.0000x reference)
#include <cuda_runtime.h>
#include <cuda_bf16.h>
#include <cstdint>

// Problem constants
#define PN   64
#define PTC  256
#define PK   32
#define PTK  64
#define PD   256
#define PV   32000
#define D4   (PD/4)
#define FULL_T (PTK + PTC)   // 320

// ---------------- scratch (device globals; no allocation allowed) ----------
__device__ float          g_P[PV * PN];          // P[v][n] = embed[v].ctx_use[n]
__device__ __nv_bfloat16  g_bhi[PN * PD];        // ctx_use hi, [n][d]
__device__ __nv_bfloat16  g_blo[PN * PD];        // ctx_use lo, [n][d]
__device__ int            g_cs[PN];
// legacy-path scratch
__device__ float          g_ctx_use[PN * PD];
__device__ float          g_know_use[PN * PK * PD];

// ---------------- helpers ---------------------------------------------------
__device__ __forceinline__ bool ck_mask_at(const unsigned char* p, int idx) {
    unsigned int w0 = *(const unsigned int*)p;
    if ((w0 & 0xFFFFFF00u) != 0u) return p[idx] != 0;       // int8 bool
    return ((const int*)p)[idx] != 0;                        // int32
}

__device__ __forceinline__ void batch8(const float4* __restrict__ e4,
                                       const int* __restrict__ toks,
                                       int t0, int j, float4& acc, float& lenf)
{
    int tk[8];
    #pragma unroll
    for (int i = 0; i < 8; i++) tk[i] = toks[t0 + i];
    float4 v[8];
    #pragma unroll
    for (int i = 0; i < 8; i++) v[i] = __ldcg(&e4[(size_t)tk[i] * D4 + j]);
    #pragma unroll
    for (int i = 0; i < 8; i++) {
        float w = (tk[i] != 0) ? 1.0f : 0.0f;
        acc.x = fmaf(w, v[i].x, acc.x); acc.y = fmaf(w, v[i].y, acc.y);
        acc.z = fmaf(w, v[i].z, acc.z); acc.w = fmaf(w, v[i].w, acc.w);
        lenf += w;
    }
}

// split one float2 into hi/lo bf16x2 registers
__device__ __forceinline__ void split2(float2 f, uint32_t& hi, uint32_t& lo) {
    __nv_bfloat162 h = __floats2bfloat162_rn(f.x, f.y);
    __nv_bfloat162 l = __floats2bfloat162_rn(f.x - __bfloat162float(h.x),
                                             f.y - __bfloat162float(h.y));
    hi = *(uint32_t*)&h;
    lo = *(uint32_t*)&l;
}

__device__ __forceinline__ void mma16816(float* d, const uint32_t* a,
                                         uint32_t b0, uint32_t b1) {
    asm volatile(
        "mma.sync.aligned.m16n8k16.row.col.f32.bf16.bf16.f32 "
        "{%0,%1,%2,%3}, {%4,%5,%6,%7}, {%8,%9}, {%0,%1,%2,%3};"
        : "+f"(d[0]), "+f"(d[1]), "+f"(d[2]), "+f"(d[3])
        : "r"(a[0]), "r"(a[1]), "r"(a[2]), "r"(a[3]), "r"(b0), "r"(b1));
}

// ---------------------------------------------------------------------------
// Kernel 1: ctx pooling (64 blocks) + fused ctx-row output gather +
// bf16 hi/lo split of normalized ctx_use (GEMM B operand, [n][d] layout).
// ---------------------------------------------------------------------------
__global__ __launch_bounds__(256, 4)
void ctx_kernel(const int* __restrict__ src_tokens,
                const float* __restrict__ embed,
                float* __restrict__ out_enc,
                float* __restrict__ out_mask)
{
    __shared__ int    toks[PTC];
    __shared__ float4 part[4][D4];
    __shared__ float  lenp[4];

    const int tid = threadIdx.x;
    const int j   = tid & 63;
    const int tq  = tid >> 6;
    const int n   = blockIdx.x;
    const float4* __restrict__ e4 = (const float4*)embed;

    toks[tid] = src_tokens[n * PTC + tid];
    __syncthreads();
    out_mask[(size_t)n * FULL_T + PTK + tid] = (toks[tid] != 0) ? 1.0f : 0.0f;

    float4 acc = make_float4(0.f, 0.f, 0.f, 0.f);
    float  lenf = 0.f;
    float4* __restrict__ oe4 = (float4*)out_enc;
    const int t0 = tq * 64;
    #pragma unroll
    for (int bt = 0; bt < 8; bt++) {
        int tk[8];
        #pragma unroll
        for (int i = 0; i < 8; i++) tk[i] = toks[t0 + bt * 8 + i];
        float4 v[8];
        #pragma unroll
        for (int i = 0; i < 8; i++) v[i] = __ldcg(&e4[(size_t)tk[i] * D4 + j]);
        #pragma unroll
        for (int i = 0; i < 8; i++) {
            const float w = (tk[i] != 0) ? 1.0f : 0.0f;
            acc.x = fmaf(w, v[i].x, acc.x); acc.y = fmaf(w, v[i].y, acc.y);
            acc.z = fmaf(w, v[i].z, acc.z); acc.w = fmaf(w, v[i].w, acc.w);
            lenf += w;
            const size_t r = (size_t)n * FULL_T + PTK + t0 + bt * 8 + i;
            __stcs(&oe4[r * D4 + j],
                   make_float4(w * v[i].x, w * v[i].y, w * v[i].z, w * v[i].w));
        }
    }

    part[tq][j] = acc;
    if (j == 0) lenp[tq] = lenf;
    __syncthreads();

    if (tq == 0) {
        float4 p0 = part[0][j], p1 = part[1][j], p2 = part[2][j], p3 = part[3][j];
        float4 a = make_float4(p0.x + p1.x + p2.x + p3.x, p0.y + p1.y + p2.y + p3.y,
                               p0.z + p1.z + p2.z + p3.z, p0.w + p1.w + p2.w + p3.w);
        float L = lenp[0] + lenp[1] + lenp[2] + lenp[3];
        float s = rsqrtf(256.0f * fmaxf(L, 1.0f));
        float2 u01 = make_float2(a.x * s, a.y * s);
        float2 u23 = make_float2(a.z * s, a.w * s);
        uint32_t h01, l01, h23, l23;
        split2(u01, h01, l01);
        split2(u23, h23, l23);
        ((uint32_t*)g_bhi)[n * 128 + 2 * j]     = h01;   // d = 4j..4j+1
        ((uint32_t*)g_bhi)[n * 128 + 2 * j + 1] = h23;   // d = 4j+2..4j+3
        ((uint32_t*)g_blo)[n * 128 + 2 * j]     = l01;
        ((uint32_t*)g_blo)[n * 128 + 2 * j + 1] = l23;
        // legacy-compatible ctx_use (used by score path only via P; keep for safety)
        ((float4*)(g_ctx_use + (size_t)n * PD))[j] =
            make_float4(u01.x, u01.y, u23.x, u23.y);
    }
}

// ---------------------------------------------------------------------------
// Kernel 2: split-bf16 mma.sync GEMM  P[v][n] = embed[v,:] . ctx_use[n,:]
// 125 CTAs x 256 thr. CTA tile M=256 (8 warps x 2 m16), N=64, K=256.
// 3 precision terms: hi*hi + hi*lo + lo*hi (f32 accumulate).
// ---------------------------------------------------------------------------
#define GEMM_M   256
#define NB_GEMM  (PV / GEMM_M)          // 125
#define BPAD     260                     // bf16 per B smem row (pad vs 256)
#define B_ROW_B  (BPAD * 2)              // 520 bytes
#define B_LO_OFF (64 * B_ROW_B)          // 33280
#define GEMM_SMEM (2 * 64 * B_ROW_B)     // 66560

__global__ __launch_bounds__(256, 1)
void gemm_kernel(const float* __restrict__ embed)
{
    extern __shared__ char smB[];        // [hi 64xBPAD][lo 64xBPAD] bf16
    const int tid  = threadIdx.x;
    const int wid  = tid >> 5;
    const int lane = tid & 31;
    const int r0   = lane >> 2;          // 0..7
    const int kq   = (lane & 3) * 2;     // 0,2,4,6

    // A base pointer: rows (warp row-block), float2 granularity (row = 128 f2)
    const int rowA = blockIdx.x * GEMM_M + wid * 32 + r0;
    const float2* __restrict__ pa = (const float2*)embed + (size_t)rowA * 128 + (kq >> 1);

    float d[2][8][4];
    #pragma unroll
    for (int mt = 0; mt < 2; mt++)
        #pragma unroll
        for (int t = 0; t < 8; t++)
            #pragma unroll
            for (int i = 0; i < 4; i++) d[mt][t][i] = 0.f;

    // ---- PDL prolog: prefetch k-step 0 of A (embed only) ----
    float2 cur[2][4];
    #pragma unroll
    for (int mt = 0; mt < 2; mt++) {
        const float2* p = pa + mt * 16 * 128;
        cur[mt][0] = __ldcg(p);
        cur[mt][1] = __ldcg(p + 8 * 128);
        cur[mt][2] = __ldcg(p + 4);
        cur[mt][3] = __ldcg(p + 8 * 128 + 4);
    }

    cudaGridDependencySynchronize();     // wait for ctx_kernel (g_bhi/g_blo)

    // ---- stage B (hi/lo) into padded smem ----
    for (int idx = tid; idx < 64 * 128; idx += 256) {
        const int n = idx >> 7;
        const int c = idx & 127;
        *(uint32_t*)(smB + n * B_ROW_B + c * 4)            = ((const uint32_t*)g_bhi)[idx];
        *(uint32_t*)(smB + B_LO_OFF + n * B_ROW_B + c * 4) = ((const uint32_t*)g_blo)[idx];
    }
    __syncthreads();

    const char* bh_base = smB + (lane >> 2) * B_ROW_B + kq * 2;  // + t*8 rows, + k step
    const char* bl_base = bh_base + B_LO_OFF;

    #pragma unroll
    for (int s = 0; s < 16; s++) {
        // prefetch next step's A
        float2 nxt[2][4];
        if (s < 15) {
            #pragma unroll
            for (int mt = 0; mt < 2; mt++) {
                const float2* p = pa + mt * 16 * 128 + (s + 1) * 8;
                nxt[mt][0] = __ldcg(p);
                nxt[mt][1] = __ldcg(p + 8 * 128);
                nxt[mt][2] = __ldcg(p + 4);
                nxt[mt][3] = __ldcg(p + 8 * 128 + 4);
            }
        }
        // convert current A to hi/lo fragments
        uint32_t ahi[2][4], alo[2][4];
        #pragma unroll
        for (int mt = 0; mt < 2; mt++)
            #pragma unroll
            for (int i = 0; i < 4; i++) split2(cur[mt][i], ahi[mt][i], alo[mt][i]);

        #pragma unroll
        for (int t = 0; t < 8; t++) {
            const int bo = t * 8 * B_ROW_B + s * 32;     // s*16 bf16 = 32 bytes
            const uint32_t bh0 = *(const uint32_t*)(bh_base + bo);
            const uint32_t bh1 = *(const uint32_t*)(bh_base + bo + 16);
            const uint32_t bl0 = *(const uint32_t*)(bl_base + bo);
            const uint32_t bl1 = *(const uint32_t*)(bl_base + bo + 16);
            #pragma unroll
            for (int mt = 0; mt < 2; mt++) {
                mma16816(d[mt][t], ahi[mt], bh0, bh1);   // hi*hi
                mma16816(d[mt][t], ahi[mt], bl0, bl1);   // hi*lo
                mma16816(d[mt][t], alo[mt], bh0, bh1);   // lo*hi
            }
        }
        #pragma unroll
        for (int mt = 0; mt < 2; mt++)
            #pragma unroll
            for (int i = 0; i < 4; i++) cur[mt][i] = nxt[mt][i];
    }

    // ---- store D to P ([v][64] f32) ----
    #pragma unroll
    for (int mt = 0; mt < 2; mt++) {
        const int row = blockIdx.x * GEMM_M + wid * 32 + mt * 16 + r0;
        #pragma unroll
        for (int t = 0; t < 8; t++) {
            const int col = t * 8 + (lane & 3) * 2;
            *(float2*)&g_P[(size_t)row * PN + col] =
                make_float2(d[mt][t][0], d[mt][t][1]);
            *(float2*)&g_P[(size_t)(row + 8) * PN + col] =
                make_float2(d[mt][t][2], d[mt][t][3]);
        }
    }
}

// ---------------------------------------------------------------------------
// Kernel 3: scores from P + argmax + ck_attn (64 blocks, PDL after GEMM).
// ---------------------------------------------------------------------------
__global__ __launch_bounds__(256)
void score_kernel(const int* __restrict__ know_tokens,
                  const unsigned char* __restrict__ ckm,
                  const int* __restrict__ cs_ids,
                  const int* __restrict__ use_cs_ids,
                  float* __restrict__ out_ck_attn)
{
    __shared__ int   toks[PK * PTK];   // 8 KB
    __shared__ float sc[PK];
    const int n    = blockIdx.x;
    const int tid  = threadIdx.x;
    const int wid  = tid >> 5;
    const int lane = tid & 31;

    // Prolog: inputs only.
    for (int idx = tid; idx < PK * PTK; idx += 256)
        toks[idx] = know_tokens[(size_t)n * PK * PTK + idx];
    const int use  = *use_cs_ids;
    const int csid = cs_ids[n];
    __syncthreads();

    cudaGridDependencySynchronize();   // wait for g_P

    #pragma unroll
    for (int kk = 0; kk < 4; kk++) {
        const int k  = wid + kk * 8;
        const int t0 = toks[k * PTK + lane];
        const int t1 = toks[k * PTK + 32 + lane];
        const float p0 = __ldcg(&g_P[(size_t)t0 * PN + n]);
        const float p1 = __ldcg(&g_P[(size_t)t1 * PN + n]);
        float dsum = ((t0 != 0) ? p0 : 0.f) + ((t1 != 0) ? p1 : 0.f);
        const int len = __popc(__ballot_sync(0xFFFFFFFFu, t0 != 0)) +
                        __popc(__ballot_sync(0xFFFFFFFFu, t1 != 0));
        #pragma unroll
        for (int o = 16; o; o >>= 1) dsum += __shfl_xor_sync(0xFFFFFFFFu, dsum, o);
        if (lane == 0) {
            const bool cm = ck_mask_at(ckm, n * PK + k);
            const float s = cm ? dsum * rsqrtf(256.0f * fmaxf((float)len, 1.0f)) : 0.0f;
            out_ck_attn[n * PK + k] = s;
            sc[k] = cm ? s : -__int_as_float(0x7f800000);
        }
    }
    __syncthreads();

    if (tid == 0) {
        int best = 0;
        float bv = -__int_as_float(0x7f800000);
        #pragma unroll
        for (int k = 0; k < PK; k++)
            if (sc[k] > bv) { bv = sc[k]; best = k; }   // first-max = jnp.argmax
        g_cs[n] = use ? csid : best;
    }
}

// ---------------------------------------------------------------------------
// Kernel 4: gather the 64 selected knowledge rows (256 blocks, PDL).
// ---------------------------------------------------------------------------
__global__ __launch_bounds__(256)
void gather_kernel(const int* __restrict__ know_tokens,
                   const unsigned char* __restrict__ ckm,
                   const float* __restrict__ embed,
                   float* __restrict__ out_enc,
                   float* __restrict__ out_mask)
{
    const int n   = blockIdx.x >> 2;
    const int prt = blockIdx.x & 3;
    const int tid = threadIdx.x;
    const int j   = tid & 63;
    const int tq  = tid >> 6;
    __shared__ int toks[16];

    cudaGridDependencySynchronize();   // wait for g_cs

    const int cs = g_cs[n];
    const int tbase = prt * 16;
    if (tid < 16) toks[tid] = know_tokens[((size_t)n * PK + cs) * PTK + tbase + tid];
    __syncthreads();
    const bool cmn = ck_mask_at(ckm, n * PK + cs);
    const float4* __restrict__ e4 = (const float4*)embed;

    int rows[4]; float ws[4]; float4 v[4];
    #pragma unroll
    for (int i = 0; i < 4; i++) {
        const int tok = toks[tq + 4 * i];
        const bool m = cmn && (tok != 0);
        ws[i] = m ? 1.0f : 0.0f;
        rows[i] = m ? tok : 0;
    }
    #pragma unroll
    for (int i = 0; i < 4; i++) v[i] = __ldcg(&e4[(size_t)rows[i] * D4 + j]);
    #pragma unroll
    for (int i = 0; i < 4; i++) {
        const size_t r = (size_t)n * FULL_T + tbase + tq + 4 * i;
        __stcs(&((float4*)out_enc)[r * D4 + j],
               make_float4(ws[i] * v[i].x, ws[i] * v[i].y, ws[i] * v[i].z, ws[i] * v[i].w));
    }
    if (tid < 16)
        out_mask[(size_t)n * FULL_T + tbase + tid] = (cmn && toks[tid] != 0) ? 1.0f : 0.0f;
}

// ===========================================================================
// LEGACY fallback (R10, proven 18.9 us) — used only if a launch API fails.
// ===========================================================================
#define LNB_CTX  PN
#define LNB_MEGA (LNB_CTX + PN * PK)

__global__ __launch_bounds__(256, 4)
void legacy_mega(const int* __restrict__ src_tokens,
                 const int* __restrict__ know_tokens,
                 const unsigned char* __restrict__ ckm,
                 const float* __restrict__ embed,
                 float* __restrict__ out_enc,
                 float* __restrict__ out_mask)
{
    __shared__ int    toks[PTC];
    __shared__ float4 part[4][D4];
    __shared__ float  lenp[4];
    const int tid = threadIdx.x, j = tid & 63, tq = tid >> 6, b = blockIdx.x;
    const float4* __restrict__ e4 = (const float4*)embed;
    float4 acc = make_float4(0.f, 0.f, 0.f, 0.f);
    float  lenf = 0.f;
    float* dst;

    if (b < LNB_CTX) {
        const int n = b;
        toks[tid] = src_tokens[n * PTC + tid];
        __syncthreads();
        out_mask[(size_t)n * FULL_T + PTK + tid] = (toks[tid] != 0) ? 1.0f : 0.0f;
        float4* __restrict__ oe4 = (float4*)out_enc;
        const int t0 = tq * 64;
        #pragma unroll
        for (int bt = 0; bt < 8; bt++) {
            int tk[8];
            #pragma unroll
            for (int i = 0; i < 8; i++) tk[i] = toks[t0 + bt * 8 + i];
            float4 v[8];
            #pragma unroll
            for (int i = 0; i < 8; i++) v[i] = __ldcg(&e4[(size_t)tk[i] * D4 + j]);
            #pragma unroll
            for (int i = 0; i < 8; i++) {
                const float w = (tk[i] != 0) ? 1.0f : 0.0f;
                acc.x = fmaf(w, v[i].x, acc.x); acc.y = fmaf(w, v[i].y, acc.y);
                acc.z = fmaf(w, v[i].z, acc.z); acc.w = fmaf(w, v[i].w, acc.w);
                lenf += w;
                const size_t r = (size_t)n * FULL_T + PTK + t0 + bt * 8 + i;
                __stcs(&oe4[r * D4 + j],
                       make_float4(w * v[i].x, w * v[i].y, w * v[i].z, w * v[i].w));
            }
        }
        dst = g_ctx_use + (size_t)n * PD;
    } else {
        const int kb = b - LNB_CTX;
        if (tid < PTK) toks[tid] = know_tokens[(size_t)kb * PTK + tid];
        __syncthreads();
        const float cmv = ck_mask_at(ckm, kb) ? 1.0f : 0.0f;
        const int t0 = tq * 16;
        batch8(e4, toks, t0, j, acc, lenf);
        batch8(e4, toks, t0 + 8, j, acc, lenf);
        acc.x *= cmv; acc.y *= cmv; acc.z *= cmv; acc.w *= cmv;
        lenf *= cmv;
        dst = g_know_use + (size_t)kb * PD;
    }
    part[tq][j] = acc;
    if (j == 0) lenp[tq] = lenf;
    __syncthreads();
    if (tq == 0) {
        float4 p0 = part[0][j], p1 = part[1][j], p2 = part[2][j], p3 = part[3][j];
        float4 a = make_float4(p0.x + p1.x + p2.x + p3.x, p0.y + p1.y + p2.y + p3.y,
                               p0.z + p1.z + p2.z + p3.z, p0.w + p1.w + p2.w + p3.w);
        float L = lenp[0] + lenp[1] + lenp[2] + lenp[3];
        float s = rsqrtf(256.0f * fmaxf(L, 1.0f));
        ((float4*)dst)[j] = make_float4(a.x * s, a.y * s, a.z * s, a.w * s);
    }
}

__global__ __launch_bounds__(256)
void legacy_tail(const int* __restrict__ know_tokens,
                 const unsigned char* __restrict__ ckm,
                 const int* __restrict__ cs_ids,
                 const int* __restrict__ use_cs_ids,
                 const float* __restrict__ embed,
                 float* __restrict__ out_enc,
                 float* __restrict__ out_mask,
                 float* __restrict__ out_ck_attn)
{
    const int n = blockIdx.x >> 2, prt = blockIdx.x & 3, tid = threadIdx.x;
    const int wid = tid >> 5, lane = tid & 31, j = tid & 63, tq = tid >> 6;
    __shared__ float scores[PK];
    __shared__ int toks[16];
    __shared__ int cs_sh;

    const int use = *use_cs_ids;
    const int cs_id_n = cs_ids[n];
    const float* __restrict__ cu = g_ctx_use + (size_t)n * PD;
    float cureg[8];
    #pragma unroll
    for (int c = 0; c < 8; c++) cureg[c] = cu[lane + 32 * c];
    #pragma unroll
    for (int kk = 0; kk < 4; kk++) {
        const int k = wid + kk * 8;
        const float* __restrict__ ku = g_know_use + ((size_t)n * PK + k) * PD;
        float p = 0.f;
        #pragma unroll
        for (int c = 0; c < 8; c++) p = fmaf(ku[lane + 32 * c], cureg[c], p);
        #pragma unroll
        for (int o = 16; o; o >>= 1) p += __shfl_xor_sync(0xFFFFFFFFu, p, o);
        if (lane == 0) scores[k] = p;
    }
    __syncthreads();
    if (tid == 0) {
        int best = 0;
        float bv = -__int_as_float(0x7f800000);
        #pragma unroll
        for (int k = 0; k < PK; k++) {
            float v = ck_mask_at(ckm, n * PK + k) ? scores[k] : -__int_as_float(0x7f800000);
            if (v > bv) { bv = v; best = k; }
        }
        cs_sh = use ? cs_id_n : best;
    }
    if (prt == 0 && tid < PK) {
        bool cm = ck_mask_at(ckm, n * PK + tid);
        out_ck_attn[n * PK + tid] = cm ? scores[tid] : 0.0f;
    }
    __syncthreads();
    const int cs = cs_sh, tbase = prt * 16;
    if (tid < 16) toks[tid] = know_tokens[((size_t)n * PK + cs) * PTK + tbase + tid];
    __syncthreads();
    const bool cmn = ck_mask_at(ckm, n * PK + cs);
    const float4* __restrict__ e4 = (const float4*)embed;
    int rows[4]; float ws[4]; float4 v[4];
    #pragma unroll
    for (int i = 0; i < 4; i++) {
        const int tok = toks[tq + 4 * i];
        const bool m = cmn && (tok != 0);
        ws[i] = m ? 1.0f : 0.0f; rows[i] = m ? tok : 0;
    }
    #pragma unroll
    for (int i = 0; i < 4; i++) v[i] = __ldcg(&e4[(size_t)rows[i] * D4 + j]);
    #pragma unroll
    for (int i = 0; i < 4; i++) {
        const size_t r = (size_t)n * FULL_T + tbase + tq + 4 * i;
        __stcs(&((float4*)out_enc)[r * D4 + j],
               make_float4(ws[i] * v[i].x, ws[i] * v[i].y, ws[i] * v[i].z, ws[i] * v[i].w));
    }
    if (tid < 16)
        out_mask[(size_t)n * FULL_T + tbase + tid] = (cmn && toks[tid] != 0) ? 1.0f : 0.0f;
}

// ---------------------------------------------------------------------------
extern "C" void kernel_launch(void* const* d_in, const int* in_sizes, int n_in,
                              void* d_out, int out_size)
{
    const int*           src_tokens  = (const int*)d_in[0];
    const int*           know_tokens = (const int*)d_in[1];
    const unsigned char* ck_mask     = (const unsigned char*)d_in[2];
    const int*           cs_ids      = (const int*)d_in[3];
    const int*           use_cs_ids  = (const int*)d_in[4];
    const float*         embed       = (const float*)d_in[5];

    float* out = (float*)d_out;
    float* out_enc     = out;
    float* out_mask    = out + (size_t)PN * FULL_T * PD;
    float* out_ck_attn = out_mask + (size_t)PN * FULL_T;

    bool fb = false;
    if (cudaFuncSetAttribute(gemm_kernel, cudaFuncAttributeMaxDynamicSharedMemorySize,
                             GEMM_SMEM) != cudaSuccess)
        fb = true;

    if (!fb) {
        ctx_kernel<<<PN, 256>>>(src_tokens, embed, out_enc, out_mask);

        cudaLaunchAttribute pdl[1];
        pdl[0].id = cudaLaunchAttributeProgrammaticStreamSerialization;
        pdl[0].val.programmaticStreamSerializationAllowed = 1;

        cudaLaunchConfig_t cg = {};
        cg.gridDim = dim3(NB_GEMM, 1, 1); cg.blockDim = dim3(256, 1, 1);
        cg.dynamicSmemBytes = GEMM_SMEM; cg.stream = 0;
        cg.attrs = pdl; cg.numAttrs = 1;
        if (cudaLaunchKernelEx(&cg, gemm_kernel, embed) != cudaSuccess) fb = true;

        if (!fb) {
            cudaLaunchConfig_t cs = {};
            cs.gridDim = dim3(PN, 1, 1); cs.blockDim = dim3(256, 1, 1);
            cs.stream = 0; cs.attrs = pdl; cs.numAttrs = 1;
            if (cudaLaunchKernelEx(&cs, score_kernel, know_tokens, ck_mask,
                                   cs_ids, use_cs_ids, out_ck_attn) != cudaSuccess)
                fb = true;
        }
        if (!fb) {
            cudaLaunchConfig_t cgk = {};
            cgk.gridDim = dim3(PN * 4, 1, 1); cgk.blockDim = dim3(256, 1, 1);
            cgk.stream = 0; cgk.attrs = pdl; cgk.numAttrs = 1;
            if (cudaLaunchKernelEx(&cgk, gather_kernel, know_tokens, ck_mask,
                                   embed, out_enc, out_mask) != cudaSuccess)
                fb = true;
        }
    }

    if (fb) {
        legacy_mega<<<LNB_MEGA, 256>>>(src_tokens, know_tokens, ck_mask, embed,
                                       out_enc, out_mask);
        legacy_tail<<<PN * 4, 256>>>(know_tokens, ck_mask, cs_ids, use_cs_ids,
                                     embed, out_enc, out_mask, out_ck_attn);
    }
}

// round 14
// speedup vs baseline: 1.7626x; 1.7626x over previous
#include <cuda_runtime.h>
#include <cuda_bf16.h>

// Problem constants
#define PN   64
#define PTC  256
#define PK   32
#define PTK  64
#define PD   256
#define D4   (PD/4)          // 64 float4 per row
#define FULL_T (PTK + PTC)   // 320

#define NB_CTX  PN                          // 64 ctx pool+gather blocks (first!)
#define NB_MEGA (NB_CTX + PN * PK)          // 64 + 2048 = 2112

// Scratch (device globals — no allocation allowed)
__device__ float g_ctx_use[PN * PD];
__device__ float g_know_use[PN * PK * PD];

// ck_mask dtype probe: jax bool may arrive as 1-byte bool or int32.
__device__ __forceinline__ bool ck_mask_at(const unsigned char* p, int idx) {
    unsigned int w0 = *(const unsigned int*)p;
    if ((w0 & 0xFFFFFF00u) != 0u) {
        return p[idx] != 0;                          // int8 bool layout
    } else {
        return ((const int*)p)[idx] != 0;            // int32 layout
    }
}

// 8-wide batched accumulate (know path): 8 independent LDG.128.CG, then FMAs.
__device__ __forceinline__ void batch8(const float4* __restrict__ e4,
                                       const int* __restrict__ toks,
                                       int t0, int j,
                                       float4& acc, float& lenf)
{
    int tk[8];
    #pragma unroll
    for (int i = 0; i < 8; i++) tk[i] = toks[t0 + i];
    float4 v[8];
    #pragma unroll
    for (int i = 0; i < 8; i++) v[i] = __ldcg(&e4[(size_t)tk[i] * D4 + j]);
    #pragma unroll
    for (int i = 0; i < 8; i++) {
        float w = (tk[i] != 0) ? 1.0f : 0.0f;
        acc.x = fmaf(w, v[i].x, acc.x);
        acc.y = fmaf(w, v[i].y, acc.y);
        acc.z = fmaf(w, v[i].z, acc.z);
        acc.w = fmaf(w, v[i].w, acc.w);
        lenf += w;
    }
}

// ---------------------------------------------------------------------------
// Mega kernel (proven R10 version), two roles:
//   b in [0, 64):      ctx pooling FUSED with ctx-row output gather.
//   b in [64, 2112):   know pooling (kb = b-64).
// ---------------------------------------------------------------------------
__global__ __launch_bounds__(256, 4)
void mega_kernel(const int* __restrict__ src_tokens,
                 const int* __restrict__ know_tokens,
                 const unsigned char* __restrict__ ckm,
                 const float* __restrict__ embed,
                 float* __restrict__ out_enc,
                 float* __restrict__ out_mask)
{
    __shared__ int    toks[PTC];
    __shared__ float4 part[4][D4];     // 4 KB
    __shared__ float  lenp[4];

    const int tid = threadIdx.x;
    const int j   = tid & 63;
    const int tq  = tid >> 6;
    const int b   = blockIdx.x;
    const float4* __restrict__ e4 = (const float4*)embed;

    float4 acc = make_float4(0.f, 0.f, 0.f, 0.f);
    float  lenf = 0.f;
    float* dst;

    if (b < NB_CTX) {
        // ---- ctx pooling + fused output gather ----
        const int n = b;
        toks[tid] = src_tokens[n * PTC + tid];
        __syncthreads();

        out_mask[(size_t)n * FULL_T + PTK + tid] = (toks[tid] != 0) ? 1.0f : 0.0f;

        float4* __restrict__ oe4 = (float4*)out_enc;
        const int t0 = tq * 64;
        #pragma unroll
        for (int bt = 0; bt < 8; bt++) {
            int tk[8];
            #pragma unroll
            for (int i = 0; i < 8; i++) tk[i] = toks[t0 + bt * 8 + i];
            float4 v[8];
            #pragma unroll
            for (int i = 0; i < 8; i++) v[i] = __ldcg(&e4[(size_t)tk[i] * D4 + j]);
            #pragma unroll
            for (int i = 0; i < 8; i++) {
                const float w = (tk[i] != 0) ? 1.0f : 0.0f;
                acc.x = fmaf(w, v[i].x, acc.x);
                acc.y = fmaf(w, v[i].y, acc.y);
                acc.z = fmaf(w, v[i].z, acc.z);
                acc.w = fmaf(w, v[i].w, acc.w);
                lenf += w;
                const size_t r = (size_t)n * FULL_T + PTK + t0 + bt * 8 + i;
                __stcs(&oe4[r * D4 + j],
                       make_float4(w * v[i].x, w * v[i].y, w * v[i].z, w * v[i].w));
            }
        }
        dst = g_ctx_use + (size_t)n * PD;
    } else {
        // ---- know pooling ----
        const int kb = b - NB_CTX;          // 0 .. 2047
        if (tid < PTK) toks[tid] = know_tokens[(size_t)kb * PTK + tid];
        __syncthreads();
        const float cmv = ck_mask_at(ckm, kb) ? 1.0f : 0.0f;

        const int t0 = tq * 16;
        batch8(e4, toks, t0,     j, acc, lenf);
        batch8(e4, toks, t0 + 8, j, acc, lenf);

        acc.x *= cmv; acc.y *= cmv; acc.z *= cmv; acc.w *= cmv;
        lenf *= cmv;
        dst = g_know_use + (size_t)kb * PD;
    }

    part[tq][j] = acc;
    if (j == 0) lenp[tq] = lenf;
    __syncthreads();

    if (tq == 0) {
        float4 p0 = part[0][j], p1 = part[1][j], p2 = part[2][j], p3 = part[3][j];
        float4 a = make_float4(p0.x + p1.x + p2.x + p3.x,
                               p0.y + p1.y + p2.y + p3.y,
                               p0.z + p1.z + p2.z + p3.z,
                               p0.w + p1.w + p2.w + p3.w);
        float L = lenp[0] + lenp[1] + lenp[2] + lenp[3];
        float s = rsqrtf(256.0f * fmaxf(L, 1.0f));
        ((float4*)dst)[j] = make_float4(a.x * s, a.y * s, a.z * s, a.w * s);
    }
}

// ---------------------------------------------------------------------------
// Tail: 2 blocks per n (128 blocks). PDL: blocks launch while mega drains,
// then wait at cudaGridDependencySynchronize() before touching its outputs.
// Each block redundantly computes the 32 scores + argmax (L2-hot, 2x instead
// of 4x redundancy), then gathers its 32 of the 64 selected knowledge rows
// (8 rows per thread-group, two 4-deep load batches). Part 0 writes ck_attn.
// ---------------------------------------------------------------------------
__global__ __launch_bounds__(256)
void tail_kernel(const int* __restrict__ know_tokens,
                 const unsigned char* __restrict__ ckm,
                 const int* __restrict__ cs_ids,
                 const int* __restrict__ use_cs_ids,
                 const float* __restrict__ embed,
                 float* __restrict__ out_enc,
                 float* __restrict__ out_mask,
                 float* __restrict__ out_ck_attn)
{
    const int n    = blockIdx.x >> 1;
    const int prt  = blockIdx.x & 1;
    const int tid  = threadIdx.x;
    const int wid  = tid >> 5;
    const int lane = tid & 31;
    const int j    = tid & 63;
    const int tq   = tid >> 6;
    __shared__ float scores[PK];
    __shared__ int   toks[32];
    __shared__ int   cs_sh;

    // Prolog on input-only data (safe before the dependency sync).
    const int use = *use_cs_ids;
    const int cs_id_n = cs_ids[n];

    // Wait for mega's g_ctx_use / g_know_use to be published.
    cudaGridDependencySynchronize();

    // ---- scores (redundant across the 2 parts; data is L2-hot) ----
    const float* __restrict__ cu = g_ctx_use + (size_t)n * PD;
    float cureg[8];
    #pragma unroll
    for (int c = 0; c < 8; c++) cureg[c] = cu[lane + 32 * c];

    #pragma unroll
    for (int kk = 0; kk < 4; kk++) {
        const int k = wid + kk * 8;
        const float* __restrict__ ku = g_know_use + ((size_t)n * PK + k) * PD;
        float p = 0.f;
        #pragma unroll
        for (int c = 0; c < 8; c++) p = fmaf(ku[lane + 32 * c], cureg[c], p);
        #pragma unroll
        for (int o = 16; o; o >>= 1) p += __shfl_xor_sync(0xFFFFFFFFu, p, o);
        if (lane == 0) scores[k] = p;
    }
    __syncthreads();

    if (tid == 0) {
        int best = 0;
        float bv = -__int_as_float(0x7f800000);  // -inf
        #pragma unroll
        for (int k = 0; k < PK; k++) {
            float v = ck_mask_at(ckm, n * PK + k) ? scores[k] : -__int_as_float(0x7f800000);
            if (v > bv) { bv = v; best = k; }   // first-max matches jnp.argmax
        }
        cs_sh = use ? cs_id_n : best;
    }
    if (prt == 0 && tid < PK) {
        bool cm = ck_mask_at(ckm, n * PK + tid);
        out_ck_attn[n * PK + tid] = cm ? scores[tid] : 0.0f;
    }
    __syncthreads();

    // ---- gather this part's 32 selected knowledge rows ----
    const int cs = cs_sh;
    const int tbase = prt * 32;
    if (tid < 32) toks[tid] = know_tokens[((size_t)n * PK + cs) * PTK + tbase + tid];
    __syncthreads();
    const bool cmn = ck_mask_at(ckm, n * PK + cs);
    const float4* __restrict__ e4 = (const float4*)embed;

    // 32 rows over 4 tq-groups -> 8 rows/thread-group, two 4-deep batches.
    #pragma unroll
    for (int g = 0; g < 2; g++) {
        int   rows[4];
        float ws[4];
        float4 v[4];
        #pragma unroll
        for (int i = 0; i < 4; i++) {
            const int t = tq + 4 * (g * 4 + i);   // local row 0..31
            const int tok = toks[t];
            const bool m = cmn && (tok != 0);
            ws[i]   = m ? 1.0f : 0.0f;
            rows[i] = m ? tok : 0;
        }
        #pragma unroll
        for (int i = 0; i < 4; i++) v[i] = __ldcg(&e4[(size_t)rows[i] * D4 + j]);
        #pragma unroll
        for (int i = 0; i < 4; i++) {
            const int t = tq + 4 * (g * 4 + i);
            const size_t r = (size_t)n * FULL_T + tbase + t;
            __stcs(&((float4*)out_enc)[r * D4 + j],
                   make_float4(ws[i] * v[i].x, ws[i] * v[i].y,
                               ws[i] * v[i].z, ws[i] * v[i].w));
        }
    }
    if (tid < 32) {
        const int tok = toks[tid];
        out_mask[(size_t)n * FULL_T + tbase + tid] = (cmn && tok != 0) ? 1.0f : 0.0f;
    }
}

// ---------------------------------------------------------------------------
extern "C" void kernel_launch(void* const* d_in, const int* in_sizes, int n_in,
                              void* d_out, int out_size)
{
    const int*           src_tokens  = (const int*)d_in[0];            // [N,TC]
    const int*           know_tokens = (const int*)d_in[1];            // [N,K,TK]
    const unsigned char* ck_mask     = (const unsigned char*)d_in[2];  // [N,K] bool
    const int*           cs_ids      = (const int*)d_in[3];            // [N]
    const int*           use_cs_ids  = (const int*)d_in[4];            // scalar
    const float*         embed       = (const float*)d_in[5];          // [V,D]

    float* out = (float*)d_out;
    float* out_enc     = out;                                   // N*320*256
    float* out_mask    = out + (size_t)PN * FULL_T * PD;        // N*320
    float* out_ck_attn = out_mask + (size_t)PN * FULL_T;        // N*K

    mega_kernel<<<NB_MEGA, 256>>>(src_tokens, know_tokens, ck_mask, embed,
                                  out_enc, out_mask);

    // Tail via PDL: launches while mega drains; waits inside the kernel.
    cudaLaunchAttribute attrs[1];
    attrs[0].id = cudaLaunchAttributeProgrammaticStreamSerialization;
    attrs[0].val.programmaticStreamSerializationAllowed = 1;

    cudaLaunchConfig_t cfg = {};
    cfg.gridDim  = dim3(PN * 2, 1, 1);
    cfg.blockDim = dim3(256, 1, 1);
    cfg.dynamicSmemBytes = 0;
    cfg.stream = 0;                    // legacy default stream (capture target)
    cfg.attrs = attrs;
    cfg.numAttrs = 1;

    cudaError_t err = cudaLaunchKernelEx(&cfg, tail_kernel,
                                         know_tokens, ck_mask, cs_ids, use_cs_ids,
                                         embed, out_enc, out_mask, out_ck_attn);
    if (err != cudaSuccess) {
        // Fallback: plain launch (cudaGridDependencySynchronize is a no-op
        // when there is no programmatic dependency).
        tail_kernel<<<PN * 2, 256>>>(know_tokens, ck_mask, cs_ids, use_cs_ids,
                                     embed, out_enc, out_mask, out_ck_attn);
    }
}

// round 15
// speedup vs baseline: 1.7716x; 1.0051x over previous
#include <cuda_runtime.h>
#include <cuda_bf16.h>

// Problem constants
#define PN   64
#define PTC  256
#define PK   32
#define PTK  64
#define PD   256
#define D4   (PD/4)          // 64 float4 per row
#define FULL_T (PTK + PTC)   // 320

#define NB_CTX  PN                          // 64 ctx pool+gather blocks (first!)
#define NB_MEGA (NB_CTX + PN * PK)          // 64 + 2048 = 2112

// Scratch (device globals — no allocation allowed)
__device__ float g_ctx_use[PN * PD];
__device__ float g_know_use[PN * PK * PD];

// ck_mask dtype probe: jax bool may arrive as 1-byte bool or int32.
__device__ __forceinline__ bool ck_mask_at(const unsigned char* p, int idx) {
    unsigned int w0 = *(const unsigned int*)p;
    if ((w0 & 0xFFFFFF00u) != 0u) {
        return p[idx] != 0;                          // int8 bool layout
    } else {
        return ((const int*)p)[idx] != 0;            // int32 layout
    }
}

// 8-wide batched accumulate (know path): 8 independent LDG.128.CG, then FMAs.
__device__ __forceinline__ void batch8(const float4* __restrict__ e4,
                                       const int* __restrict__ toks,
                                       int t0, int j,
                                       float4& acc, float& lenf)
{
    int tk[8];
    #pragma unroll
    for (int i = 0; i < 8; i++) tk[i] = toks[t0 + i];
    float4 v[8];
    #pragma unroll
    for (int i = 0; i < 8; i++) v[i] = __ldcg(&e4[(size_t)tk[i] * D4 + j]);
    #pragma unroll
    for (int i = 0; i < 8; i++) {
        float w = (tk[i] != 0) ? 1.0f : 0.0f;
        acc.x = fmaf(w, v[i].x, acc.x);
        acc.y = fmaf(w, v[i].y, acc.y);
        acc.z = fmaf(w, v[i].z, acc.z);
        acc.w = fmaf(w, v[i].w, acc.w);
        lenf += w;
    }
}

// ---------------------------------------------------------------------------
// Mega kernel, two roles:
//   b in [0, 64):      ctx pooling FUSED with ctx-row output gather: every
//                      embed fragment loaded for pooling is also written
//                      (masked) to full_enc — no redundant ctx re-reads.
//   b in [64, 2112):   know pooling (kb = b-64).
// 256 threads, j = tid & 63 (float4 column), tq = tid >> 6 (token group).
// ---------------------------------------------------------------------------
__global__ __launch_bounds__(256, 4)
void mega_kernel(const int* __restrict__ src_tokens,
                 const int* __restrict__ know_tokens,
                 const unsigned char* __restrict__ ckm,
                 const float* __restrict__ embed,
                 float* __restrict__ out_enc,
                 float* __restrict__ out_mask)
{
    __shared__ int    toks[PTC];
    __shared__ float4 part[4][D4];     // 4 KB
    __shared__ float  lenp[4];

    const int tid = threadIdx.x;
    const int j   = tid & 63;
    const int tq  = tid >> 6;
    const int b   = blockIdx.x;
    const float4* __restrict__ e4 = (const float4*)embed;

    float4 acc = make_float4(0.f, 0.f, 0.f, 0.f);
    float  lenf = 0.f;
    float* dst;

    if (b < NB_CTX) {
        // ---- ctx pooling + fused output gather ----
        const int n = b;
        toks[tid] = src_tokens[n * PTC + tid];
        __syncthreads();

        out_mask[(size_t)n * FULL_T + PTK + tid] = (toks[tid] != 0) ? 1.0f : 0.0f;

        float4* __restrict__ oe4 = (float4*)out_enc;
        const int t0 = tq * 64;
        #pragma unroll
        for (int bt = 0; bt < 8; bt++) {
            int tk[8];
            #pragma unroll
            for (int i = 0; i < 8; i++) tk[i] = toks[t0 + bt * 8 + i];
            float4 v[8];
            #pragma unroll
            for (int i = 0; i < 8; i++) v[i] = __ldcg(&e4[(size_t)tk[i] * D4 + j]);
            #pragma unroll
            for (int i = 0; i < 8; i++) {
                const float w = (tk[i] != 0) ? 1.0f : 0.0f;
                acc.x = fmaf(w, v[i].x, acc.x);
                acc.y = fmaf(w, v[i].y, acc.y);
                acc.z = fmaf(w, v[i].z, acc.z);
                acc.w = fmaf(w, v[i].w, acc.w);
                lenf += w;
                const size_t r = (size_t)n * FULL_T + PTK + t0 + bt * 8 + i;
                __stcs(&oe4[r * D4 + j],
                       make_float4(w * v[i].x, w * v[i].y, w * v[i].z, w * v[i].w));
            }
        }
        dst = g_ctx_use + (size_t)n * PD;
    } else {
        // ---- know pooling ----
        const int kb = b - NB_CTX;          // 0 .. 2047
        if (tid < PTK) toks[tid] = know_tokens[(size_t)kb * PTK + tid];
        __syncthreads();
        const float cmv = ck_mask_at(ckm, kb) ? 1.0f : 0.0f;

        const int t0 = tq * 16;
        batch8(e4, toks, t0,     j, acc, lenf);
        batch8(e4, toks, t0 + 8, j, acc, lenf);

        acc.x *= cmv; acc.y *= cmv; acc.z *= cmv; acc.w *= cmv;
        lenf *= cmv;
        dst = g_know_use + (size_t)kb * PD;
    }

    part[tq][j] = acc;
    if (j == 0) lenp[tq] = lenf;
    __syncthreads();

    if (tq == 0) {
        float4 p0 = part[0][j], p1 = part[1][j], p2 = part[2][j], p3 = part[3][j];
        float4 a = make_float4(p0.x + p1.x + p2.x + p3.x,
                               p0.y + p1.y + p2.y + p3.y,
                               p0.z + p1.z + p2.z + p3.z,
                               p0.w + p1.w + p2.w + p3.w);
        float L = lenp[0] + lenp[1] + lenp[2] + lenp[3];
        float s = rsqrtf(256.0f * fmaxf(L, 1.0f));
        ((float4*)dst)[j] = make_float4(a.x * s, a.y * s, a.z * s, a.w * s);
    }
}

// ---------------------------------------------------------------------------
// Tail: 4 blocks per n (256 blocks). PDL: blocks launch while mega drains,
// then wait at cudaGridDependencySynchronize() before touching its outputs.
// Each block redundantly computes the 32 scores + argmax (L2-hot), then
// gathers its 16 of the 64 selected knowledge rows. Part 0 writes ck_attn.
// ---------------------------------------------------------------------------
__global__ __launch_bounds__(256)
void tail_kernel(const int* __restrict__ know_tokens,
                 const unsigned char* __restrict__ ckm,
                 const int* __restrict__ cs_ids,
                 const int* __restrict__ use_cs_ids,
                 const float* __restrict__ embed,
                 float* __restrict__ out_enc,
                 float* __restrict__ out_mask,
                 float* __restrict__ out_ck_attn)
{
    const int n    = blockIdx.x >> 2;
    const int prt  = blockIdx.x & 3;
    const int tid  = threadIdx.x;
    const int wid  = tid >> 5;
    const int lane = tid & 31;
    const int j    = tid & 63;
    const int tq   = tid >> 6;
    __shared__ float scores[PK];
    __shared__ int   toks[16];
    __shared__ int   cs_sh;

    // Prolog on input-only data (safe before the dependency sync).
    const int use = *use_cs_ids;
    const int cs_id_n = cs_ids[n];

    // Wait for mega's g_ctx_use / g_know_use to be published.
    cudaGridDependencySynchronize();

    // ---- scores (redundant across the 4 parts; data is L2-hot) ----
    const float* __restrict__ cu = g_ctx_use + (size_t)n * PD;
    float cureg[8];
    #pragma unroll
    for (int c = 0; c < 8; c++) cureg[c] = cu[lane + 32 * c];

    #pragma unroll
    for (int kk = 0; kk < 4; kk++) {
        const int k = wid + kk * 8;
        const float* __restrict__ ku = g_know_use + ((size_t)n * PK + k) * PD;
        float p = 0.f;
        #pragma unroll
        for (int c = 0; c < 8; c++) p = fmaf(ku[lane + 32 * c], cureg[c], p);
        #pragma unroll
        for (int o = 16; o; o >>= 1) p += __shfl_xor_sync(0xFFFFFFFFu, p, o);
        if (lane == 0) scores[k] = p;
    }
    __syncthreads();

    if (tid == 0) {
        int best = 0;
        float bv = -__int_as_float(0x7f800000);  // -inf
        #pragma unroll
        for (int k = 0; k < PK; k++) {
            float v = ck_mask_at(ckm, n * PK + k) ? scores[k] : -__int_as_float(0x7f800000);
            if (v > bv) { bv = v; best = k; }   // first-max matches jnp.argmax
        }
        cs_sh = use ? cs_id_n : best;
    }
    if (prt == 0 && tid < PK) {
        bool cm = ck_mask_at(ckm, n * PK + tid);
        out_ck_attn[n * PK + tid] = cm ? scores[tid] : 0.0f;
    }
    __syncthreads();

    // ---- gather this part's 16 selected knowledge rows ----
    const int cs = cs_sh;
    const int tbase = prt * 16;
    if (tid < 16) toks[tid] = know_tokens[((size_t)n * PK + cs) * PTK + tbase + tid];
    __syncthreads();
    const bool cmn = ck_mask_at(ckm, n * PK + cs);
    const float4* __restrict__ e4 = (const float4*)embed;

    // 16 rows over 4 tq-groups -> 4 rows/thread-group, 4-deep batched.
    int   rows[4];
    float ws[4];
    float4 v[4];
    #pragma unroll
    for (int i = 0; i < 4; i++) {
        const int t = tq + 4 * i;              // local row 0..15
        const int tok = toks[t];
        const bool m = cmn && (tok != 0);
        ws[i]   = m ? 1.0f : 0.0f;
        rows[i] = m ? tok : 0;
    }
    #pragma unroll
    for (int i = 0; i < 4; i++) v[i] = __ldcg(&e4[(size_t)rows[i] * D4 + j]);
    #pragma unroll
    for (int i = 0; i < 4; i++) {
        const int t = tq + 4 * i;
        const size_t r = (size_t)n * FULL_T + tbase + t;
        __stcs(&((float4*)out_enc)[r * D4 + j],
               make_float4(ws[i] * v[i].x, ws[i] * v[i].y,
                           ws[i] * v[i].z, ws[i] * v[i].w));
    }
    if (tid < 16) {
        const int tok = toks[tid];
        out_mask[(size_t)n * FULL_T + tbase + tid] = (cmn && tok != 0) ? 1.0f : 0.0f;
    }
}

// ---------------------------------------------------------------------------
extern "C" void kernel_launch(void* const* d_in, const int* in_sizes, int n_in,
                              void* d_out, int out_size)
{
    const int*           src_tokens  = (const int*)d_in[0];            // [N,TC]
    const int*           know_tokens = (const int*)d_in[1];            // [N,K,TK]
    const unsigned char* ck_mask     = (const unsigned char*)d_in[2];  // [N,K] bool
    const int*           cs_ids      = (const int*)d_in[3];            // [N]
    const int*           use_cs_ids  = (const int*)d_in[4];            // scalar
    const float*         embed       = (const float*)d_in[5];          // [V,D]

    float* out = (float*)d_out;
    float* out_enc     = out;                                   // N*320*256
    float* out_mask    = out + (size_t)PN * FULL_T * PD;        // N*320
    float* out_ck_attn = out_mask + (size_t)PN * FULL_T;        // N*K

    mega_kernel<<<NB_MEGA, 256>>>(src_tokens, know_tokens, ck_mask, embed,
                                  out_enc, out_mask);

    // Tail via PDL: launches while mega drains; waits inside the kernel.
    cudaLaunchAttribute attrs[1];
    attrs[0].id = cudaLaunchAttributeProgrammaticStreamSerialization;
    attrs[0].val.programmaticStreamSerializationAllowed = 1;

    cudaLaunchConfig_t cfg = {};
    cfg.gridDim  = dim3(PN * 4, 1, 1);
    cfg.blockDim = dim3(256, 1, 1);
    cfg.dynamicSmemBytes = 0;
    cfg.stream = 0;                    // legacy default stream (capture target)
    cfg.attrs = attrs;
    cfg.numAttrs = 1;

    cudaError_t err = cudaLaunchKernelEx(&cfg, tail_kernel,
                                         know_tokens, ck_mask, cs_ids, use_cs_ids,
                                         embed, out_enc, out_mask, out_ck_attn);
    if (err != cudaSuccess) {
        // Fallback: plain launch (cudaGridDependencySynchronize is a no-op
        // when there is no programmatic dependency).
        tail_kernel<<<PN * 4, 256>>>(know_tokens, ck_mask, cs_ids, use_cs_ids,
                                     embed, out_enc, out_mask, out_ck_attn);
    }
}